// round 2
// baseline (speedup 1.0000x reference)
#include <cuda_runtime.h>

#define NN 200000
#define NE 800000
#define NG 4096
#define KDRUG 78
#define KCELL 954
#define HF 128
#define BN_EPS 1e-5f

// ---------------- scratch (static __device__ globals; no allocation) ----------------
__device__ float g_deg[NN];
__device__ float g_dinv[NN];
__device__ float g_t[NN];          // dinv_i + sum_{s->i} dinv_s
__device__ float g_h[(size_t)NN * HF];   // h1 / h2
__device__ float g_x[(size_t)NN * HF];   // out1 / out2
__device__ float g_stat1[2 * HF];
__device__ float g_stat2[2 * HF];
__device__ float g_statc[2 * HF];
__device__ float g_W2p[HF * HF];
__device__ float g_c2[HF];
__device__ float g_Wc2p[HF * HF];
__device__ float g_bc2p[HF];
__device__ float g_smax[NG * HF];
__device__ float g_smin[NG * HF];
__device__ float g_sc2[HF];
__device__ float g_sh2[HF];
__device__ float g_cell[(size_t)NG * HF];

__device__ __forceinline__ float neg_inf() { return __int_as_float(0xff800000); }
__device__ __forceinline__ float pos_inf() { return __int_as_float(0x7f800000); }

// ---------------- init ----------------
__global__ void k_init() {
    int i = blockIdx.x * blockDim.x + threadIdx.x;
    if (i < NN) g_deg[i] = 1.0f;           // self loop
    if (i < 2 * HF) { g_stat1[i] = 0.f; g_stat2[i] = 0.f; g_statc[i] = 0.f; }
}

__global__ void k_edge_deg(const int* __restrict__ ei) {
    int e = blockIdx.x * blockDim.x + threadIdx.x;
    if (e < NE) atomicAdd(&g_deg[ei[NE + e]], 1.0f);
}

__global__ void k_dinv() {
    int i = blockIdx.x * blockDim.x + threadIdx.x;
    if (i < NN) {
        float d = rsqrtf(fmaxf(g_deg[i], 1e-12f));
        g_dinv[i] = d;
        g_t[i] = d;  // self term of t
    }
}

__global__ void k_edge_t(const int* __restrict__ ei) {
    int e = blockIdx.x * blockDim.x + threadIdx.x;
    if (e < NE) {
        int s = ei[e], d = ei[NE + e];
        atomicAdd(&g_t[d], g_dinv[s]);
    }
}

// ---------------- generic tiled GEMM: C[Mx128] = act(A[MxK] @ B[Kx128] + bias) ----------------
// ACT: 0 = none (no bias), 1 = +bias, 2 = tanh(+bias), 3 = relu(+bias)
template <int ACT, bool RELUIN>
__global__ void __launch_bounds__(256) gemm128_k(const float* __restrict__ A,
                                                 const float* __restrict__ B,
                                                 const float* __restrict__ bias,
                                                 float* __restrict__ C, int M, int K) {
    __shared__ float As[64][65];
    __shared__ float Bs[64][128];
    int tid = threadIdx.x;
    int tc = tid & 31;        // col group: cols 4*tc .. 4*tc+3
    int tr = tid >> 5;        // row group: rows 8*tr .. 8*tr+7
    int row0 = blockIdx.x * 64;

    float acc[8][4];
#pragma unroll
    for (int r = 0; r < 8; r++)
#pragma unroll
        for (int c = 0; c < 4; c++) acc[r][c] = 0.f;

    for (int k0 = 0; k0 < K; k0 += 64) {
#pragma unroll
        for (int idx = tid; idx < 64 * 64; idx += 256) {
            int r = idx >> 6, kk = idx & 63;
            int k = k0 + kk;
            float v = (k < K) ? A[(size_t)(row0 + r) * K + k] : 0.f;
            if (RELUIN) v = fmaxf(v, 0.f);
            As[kk][r] = v;
        }
#pragma unroll
        for (int idx = tid; idx < 64 * 128; idx += 256) {
            int kk = idx >> 7, n = idx & 127;
            int k = k0 + kk;
            Bs[kk][n] = (k < K) ? B[k * 128 + n] : 0.f;
        }
        __syncthreads();
#pragma unroll 16
        for (int kk = 0; kk < 64; kk++) {
            float4 b = *(const float4*)&Bs[kk][tc * 4];
#pragma unroll
            for (int r = 0; r < 8; r++) {
                float a = As[kk][tr * 8 + r];
                acc[r][0] += a * b.x;
                acc[r][1] += a * b.y;
                acc[r][2] += a * b.z;
                acc[r][3] += a * b.w;
            }
        }
        __syncthreads();
    }

    float4 bv = make_float4(0.f, 0.f, 0.f, 0.f);
    if (ACT >= 1) bv = *(const float4*)&bias[tc * 4];
#pragma unroll
    for (int r = 0; r < 8; r++) {
        float4 v;
        v.x = acc[r][0] + bv.x;
        v.y = acc[r][1] + bv.y;
        v.z = acc[r][2] + bv.z;
        v.w = acc[r][3] + bv.w;
        if (ACT == 2) { v.x = tanhf(v.x); v.y = tanhf(v.y); v.z = tanhf(v.z); v.w = tanhf(v.w); }
        if (ACT == 3) {
            v.x = fmaxf(v.x, 0.f); v.y = fmaxf(v.y, 0.f);
            v.z = fmaxf(v.z, 0.f); v.w = fmaxf(v.w, 0.f);
        }
        *(float4*)&C[(size_t)(row0 + tr * 8 + r) * 128 + tc * 4] = v;
    }
}

// ---------------- out init: out[i,:] = h[i,:]*dinv_i^2 (+ s_i*c[:]) + bias[:] ----------------
template <bool WITHC>
__global__ void k_init_out(const float* __restrict__ h, const float* __restrict__ bias,
                           const float* __restrict__ cvec, float* __restrict__ out) {
    int idx = blockIdx.x * blockDim.x + threadIdx.x;  // over NN*32 float4 slots
    if (idx >= NN * 32) return;
    int i = idx >> 5, q = idx & 31;
    float di = g_dinv[i];
    float a = di * di;
    float4 hv = ((const float4*)h)[idx];
    float4 bb = ((const float4*)bias)[q];
    float4 o;
    if (WITHC) {
        float s = di * g_t[i];
        float4 cv = ((const float4*)cvec)[q];
        o.x = hv.x * a + s * cv.x + bb.x;
        o.y = hv.y * a + s * cv.y + bb.y;
        o.z = hv.z * a + s * cv.z + bb.z;
        o.w = hv.w * a + s * cv.w + bb.w;
    } else {
        o.x = hv.x * a + bb.x;
        o.y = hv.y * a + bb.y;
        o.z = hv.z * a + bb.z;
        o.w = hv.w * a + bb.w;
    }
    ((float4*)out)[idx] = o;
}

// ---------------- edge scatter: out[d,:] += h[s,:]*dinv_s*dinv_d (vector red) ----------------
__global__ void k_scatter(const int* __restrict__ ei, const float* __restrict__ h,
                          float* __restrict__ out) {
    int t = blockIdx.x * blockDim.x + threadIdx.x;
    int e = t >> 5, lane = t & 31;
    if (e >= NE) return;
    int s = ei[e], d = ei[NE + e];
    float w = g_dinv[s] * g_dinv[d];
    float4 v = ((const float4*)h)[(size_t)s * 32 + lane];
    v.x *= w; v.y *= w; v.z *= w; v.w *= w;
    float* p = out + (size_t)d * HF + lane * 4;
    asm volatile("red.global.add.v4.f32 [%0], {%1,%2,%3,%4};"
                 :: "l"(p), "f"(v.x), "f"(v.y), "f"(v.z), "f"(v.w) : "memory");
}

// ---------------- column stats (sum, sumsq), optional relu ----------------
template <bool RELU>
__global__ void k_stats(const float* __restrict__ x, float* __restrict__ stat, int nrows) {
    __shared__ float ss[2 * HF];
    int tid = threadIdx.x;
    int lane = tid & 31, warp = tid >> 5;
    float4 s = make_float4(0.f, 0.f, 0.f, 0.f);
    float4 q = make_float4(0.f, 0.f, 0.f, 0.f);
    for (int i = blockIdx.x * 8 + warp; i < nrows; i += gridDim.x * 8) {
        float4 v = ((const float4*)x)[(size_t)i * 32 + lane];
        if (RELU) {
            v.x = fmaxf(v.x, 0.f); v.y = fmaxf(v.y, 0.f);
            v.z = fmaxf(v.z, 0.f); v.w = fmaxf(v.w, 0.f);
        }
        s.x += v.x; s.y += v.y; s.z += v.z; s.w += v.w;
        q.x += v.x * v.x; q.y += v.y * v.y; q.z += v.z * v.z; q.w += v.w * v.w;
    }
    for (int j = tid; j < 2 * HF; j += blockDim.x) ss[j] = 0.f;
    __syncthreads();
    atomicAdd(&ss[lane * 4 + 0], s.x);
    atomicAdd(&ss[lane * 4 + 1], s.y);
    atomicAdd(&ss[lane * 4 + 2], s.z);
    atomicAdd(&ss[lane * 4 + 3], s.w);
    atomicAdd(&ss[HF + lane * 4 + 0], q.x);
    atomicAdd(&ss[HF + lane * 4 + 1], q.y);
    atomicAdd(&ss[HF + lane * 4 + 2], q.z);
    atomicAdd(&ss[HF + lane * 4 + 3], q.w);
    __syncthreads();
    for (int j = tid; j < 2 * HF; j += blockDim.x) atomicAdd(&stat[j], ss[j]);
}

// ---------------- fold BN1 into W2 (W2p = diag(scale1)@W2, c2 = shift1@W2) ----------------
__global__ void k_fold1(const float* __restrict__ g1, const float* __restrict__ be1,
                        const float* __restrict__ W2) {
    __shared__ float sc[HF], sh[HF];
    int n = threadIdx.x;
    float mu = g_stat1[n] * (1.0f / NN);
    float var = g_stat1[HF + n] * (1.0f / NN) - mu * mu;
    float s = g1[n] * rsqrtf(var + BN_EPS);
    sc[n] = s;
    sh[n] = be1[n] - mu * s;
    __syncthreads();
    float c = 0.f;
#pragma unroll 8
    for (int k = 0; k < HF; k++) {
        float w = W2[k * HF + n];
        g_W2p[k * HF + n] = sc[k] * w;
        c += sh[k] * w;
    }
    g_c2[n] = c;
}

// ---------------- fold cell BN into Wc2 ----------------
__global__ void k_foldc(const float* __restrict__ gc1, const float* __restrict__ bec1,
                        const float* __restrict__ Wc2, const float* __restrict__ bc2) {
    __shared__ float sc[HF], sh[HF];
    int n = threadIdx.x;
    float mu = g_statc[n] * (1.0f / NG);
    float var = g_statc[HF + n] * (1.0f / NG) - mu * mu;
    float s = gc1[n] * rsqrtf(var + BN_EPS);
    sc[n] = s;
    sh[n] = bec1[n] - mu * s;
    __syncthreads();
    float c = 0.f;
#pragma unroll 8
    for (int k = 0; k < HF; k++) {
        float w = Wc2[k * HF + n];
        g_Wc2p[k * HF + n] = sc[k] * w;
        c += sh[k] * w;
    }
    g_bc2p[n] = bc2[n] + c;
}

// ---------------- per-graph pool: max/min of relu(out2), fused BN2 stats ----------------
__global__ void k_pool(const int* __restrict__ ib) {
    int g = blockIdx.x;
    int lo = 0, hi = NN;
    while (lo < hi) { int m = (lo + hi) >> 1; if (ib[m] < g) lo = m + 1; else hi = m; }
    int start = lo;
    hi = NN;
    while (lo < hi) { int m = (lo + hi) >> 1; if (ib[m] < g + 1) lo = m + 1; else hi = m; }
    int end = lo;

    int k = threadIdx.x;
    float mx = neg_inf(), mn = pos_inf(), s = 0.f, q = 0.f;
    for (int i = start; i < end; i++) {
        float v = fmaxf(g_x[(size_t)i * HF + k], 0.f);
        mx = fmaxf(mx, v);
        mn = fminf(mn, v);
        s += v;
        q += v * v;
    }
    g_smax[g * HF + k] = mx;
    g_smin[g * HF + k] = mn;
    if (end > start) {
        atomicAdd(&g_stat2[k], s);
        atomicAdd(&g_stat2[HF + k], q);
    }
}

__global__ void k_scale2(const float* __restrict__ g2, const float* __restrict__ be2) {
    int n = threadIdx.x;
    float mu = g_stat2[n] * (1.0f / NN);
    float var = g_stat2[HF + n] * (1.0f / NN) - mu * mu;
    float s = g2[n] * rsqrtf(var + BN_EPS);
    g_sc2[n] = s;
    g_sh2[n] = be2[n] - mu * s;
}

__global__ void k_final(float* __restrict__ out) {
    int idx = blockIdx.x * blockDim.x + threadIdx.x;
    if (idx >= NG * HF) return;
    int k = idx & 127;
    float mx = g_smax[idx];
    float r;
    if (mx == neg_inf()) {
        r = neg_inf();  // empty segment: segment_max identity
    } else {
        float s = g_sc2[k];
        float v = (s >= 0.f) ? mx : g_smin[idx];
        r = s * v + g_sh2[k];
    }
    out[idx] = r;
}

// ---------------- host ----------------
extern "C" void kernel_launch(void* const* d_in, const int* in_sizes, int n_in,
                              void* d_out, int out_size) {
    const float* drug = (const float*)d_in[0];
    const int* ei = (const int*)d_in[1];      // int32! (JAX x64 disabled)
    const int* ib = (const int*)d_in[2];      // int32!
    const float* gexpr = (const float*)d_in[3];
    const float* W1 = (const float*)d_in[4];
    const float* b1 = (const float*)d_in[5];
    const float* g1 = (const float*)d_in[6];
    const float* be1 = (const float*)d_in[7];
    const float* W2 = (const float*)d_in[8];
    const float* b2 = (const float*)d_in[9];
    const float* g2 = (const float*)d_in[10];
    const float* be2 = (const float*)d_in[11];
    const float* Wc1 = (const float*)d_in[12];
    const float* bc1 = (const float*)d_in[13];
    const float* gc1 = (const float*)d_in[14];
    const float* bec1 = (const float*)d_in[15];
    const float* Wc2 = (const float*)d_in[16];
    const float* bc2 = (const float*)d_in[17];
    float* out = (float*)d_out;

    float *hp, *xp, *cellp, *stat1p, *statcp, *W2pp, *c2p, *Wc2pp, *bc2pp;
    cudaGetSymbolAddress((void**)&hp, g_h);
    cudaGetSymbolAddress((void**)&xp, g_x);
    cudaGetSymbolAddress((void**)&cellp, g_cell);
    cudaGetSymbolAddress((void**)&stat1p, g_stat1);
    cudaGetSymbolAddress((void**)&statcp, g_statc);
    cudaGetSymbolAddress((void**)&W2pp, g_W2p);
    cudaGetSymbolAddress((void**)&c2p, g_c2);
    cudaGetSymbolAddress((void**)&Wc2pp, g_Wc2p);
    cudaGetSymbolAddress((void**)&bc2pp, g_bc2p);

    // graph normalization (shared by both GCN layers)
    k_init<<<(NN + 255) / 256, 256>>>();
    k_edge_deg<<<(NE + 255) / 256, 256>>>(ei);
    k_dinv<<<(NN + 255) / 256, 256>>>();
    k_edge_t<<<(NE + 255) / 256, 256>>>(ei);

    // GCN layer 1
    gemm128_k<0, false><<<NN / 64, 256>>>(drug, W1, nullptr, hp, NN, KDRUG);
    k_init_out<false><<<(NN * 32 + 255) / 256, 256>>>(hp, b1, nullptr, xp);
    k_scatter<<<(NE * 32 + 255) / 256, 256>>>(ei, hp, xp);

    // BN1 stats over relu(out1), fold into W2
    k_stats<true><<<1024, 256>>>(xp, stat1p, NN);
    k_fold1<<<1, HF>>>(g1, be1, W2);

    // GCN layer 2 (relu applied at A load; BN1 folded into W2p; shift via s_i*c2)
    gemm128_k<0, true><<<NN / 64, 256>>>(xp, W2pp, nullptr, hp, NN, HF);
    k_init_out<true><<<(NN * 32 + 255) / 256, 256>>>(hp, b2, c2p, xp);
    k_scatter<<<(NE * 32 + 255) / 256, 256>>>(ei, hp, xp);

    // pool (max/min of relu) + BN2 stats fused, then BN2-folded select
    k_pool<<<NG, HF>>>(ib);
    k_scale2<<<1, HF>>>(g2, be2);
    k_final<<<(NG * HF + 255) / 256, 256>>>(out);

    // cell branch
    gemm128_k<2, false><<<NG / 64, 256>>>(gexpr, Wc1, bc1, cellp, NG, KCELL);
    k_stats<false><<<64, 256>>>(cellp, statcp, NG);
    k_foldc<<<1, HF>>>(gc1, bec1, Wc2, bc2);
    gemm128_k<3, false><<<NG / 64, 256>>>(cellp, Wc2pp, bc2pp, out + NG * HF, NG, HF);
}